// round 7
// baseline (speedup 1.0000x reference)
#include <cuda_runtime.h>
#include <cuda_bf16.h>

// Problem constants (match reference)
#define WPIX 512.0f
#define HPIX 512.0f
#define S_MIN (1.0f / 30.0f)
#define S_MAX (1.0f / 0.75f)
#define MU_BORDER 1.05f
#define PI_APPROX 3.1416f

#define MAX_N 512            // actual N = 512 (asserted via min() clamps)
#define MAX_B 65536
#define TILE_PX 16.0f
#define TILES_X 32
#define TILES_Y 32
#define NUM_TILES (TILES_X * TILES_Y)
#define GC 64                // gaussians staged per smem chunk

// ---- per-gaussian precomputed data ----
__device__ float4 g_ga[MAX_N];          // (gmx, gmy, Sx, Sy), centered px coords
__device__ float4 g_gb[MAX_N];          // (cos a, sin a, sigmoid(op), 0)
__device__ float4 g_sh[MAX_N * 7];      // repacked 27 SH coeffs + pad
__device__ float4 g_bbox[MAX_N];        // (xmin, xmax, ymin, ymax), raw px

// ---- ray binning (counting sort by tile) ----
__device__ int    g_hist[NUM_TILES];    // .bss zero; re-zeroed by splat each call
__device__ int    g_base[NUM_TILES];
__device__ int    g_rank[MAX_B];
__device__ float2 g_xy[MAX_B];          // sorted ray coords
__device__ int    g_rayid[MAX_B];       // sorted ray ids

__device__ __forceinline__ int tile_of(float xr, float yr) {
    int tx = min(TILES_X - 1, max(0, (int)(xr * (1.0f / TILE_PX))));
    int ty = min(TILES_Y - 1, max(0, (int)(yr * (1.0f / TILE_PX))));
    return ty * TILES_X + tx;
}

// ============================================================================
// K1: blocks [0, binBlocks): ray binning (hist + rank)
//     block binBlocks: per-gaussian precompute (ga, gb, sh, bbox) — ONCE
// ============================================================================
__global__ __launch_bounds__(512)
void prep_kernel(const float* __restrict__ x,
                 const float* __restrict__ rgbsh,
                 const float* __restrict__ opacity,
                 const float* __restrict__ mu,
                 const float* __restrict__ scale,
                 const float* __restrict__ angle,
                 int B, int N, int binBlocks) {
    int bid = blockIdx.x;
    int tid = threadIdx.x;

    if (bid < binBlocks) {
        int r = bid * 512 + tid;
        if (r < B) {
            float xr = x[2 * r + 0];
            float yr = x[2 * r + 1];
            int t = tile_of(xr, yr);
            g_rank[r] = atomicAdd(&g_hist[t], 1);
        }
    } else {
        for (int n = tid; n < N; n += 512) {
            float gmx = tanhf(mu[2 * n + 0]) * (MU_BORDER * WPIX * 0.5f);
            float gmy = tanhf(mu[2 * n + 1]) * (MU_BORDER * HPIX * 0.5f);
            float sx = fminf(fmaxf(scale[2 * n + 0], 0.0f), 1.0f) * (S_MAX - S_MIN) + S_MIN;
            float sy = fminf(fmaxf(scale[2 * n + 1], 0.0f), 1.0f) * (S_MAX - S_MIN) + S_MIN;
            g_ga[n] = make_float4(gmx, gmy, sx, sy);

            float hx = __fdividef(5.0f, sx) + 0.05f;   // fp-rounding margin
            float hy = __fdividef(5.0f, sy) + 0.05f;
            float cx = gmx + WPIX * 0.5f;
            float cy = gmy + HPIX * 0.5f;
            g_bbox[n] = make_float4(cx - hx, cx + hx, cy - hy, cy + hy);

            float alpha = tanhf(angle[n]) * PI_APPROX;
            float c, s;
            sincosf(alpha, &s, &c);
            float op = 1.0f / (1.0f + expf(-opacity[n]));
            g_gb[n] = make_float4(c, s, op, 0.0f);

            float v[28];
#pragma unroll
            for (int m = 0; m < 27; ++m) v[m] = rgbsh[n * 27 + m];
            v[27] = 0.0f;
#pragma unroll
            for (int j = 0; j < 7; ++j)
                g_sh[n * 7 + j] = make_float4(v[4 * j], v[4 * j + 1], v[4 * j + 2], v[4 * j + 3]);
        }
    }
}

// ============================================================================
// K2: every block redundantly scans the 1024-bin histogram in smem, then
// scatters its 1024-ray slice into sorted order (coords + id).
// Block 0 publishes g_base.
// ============================================================================
__global__ __launch_bounds__(NUM_TILES)
void scan_scatter_kernel(const float* __restrict__ x, int B) {
    __shared__ int buf[NUM_TILES];
    __shared__ int sbase[NUM_TILES];
    int t = threadIdx.x;
    int h = g_hist[t];
    buf[t] = h;
    __syncthreads();
#pragma unroll
    for (int off = 1; off < NUM_TILES; off <<= 1) {
        int v = (t >= off) ? buf[t - off] : 0;
        __syncthreads();
        buf[t] += v;
        __syncthreads();
    }
    sbase[t] = buf[t] - h;   // exclusive
    if (blockIdx.x == 0) g_base[t] = sbase[t];
    __syncthreads();

    int r = blockIdx.x * NUM_TILES + t;
    if (r < B) {
        float xr = x[2 * r + 0];
        float yr = x[2 * r + 1];
        int tr = tile_of(xr, yr);
        int pos = sbase[tr] + g_rank[r];
        g_xy[pos] = make_float2(xr, yr);
        g_rayid[pos] = r;
    }
}

// ============================================================================
// K3: splat — one block per tile. Builds its own gaussian list inline in smem
// (parallel bbox tests -> ballot masks -> ordered compaction), stages gaussian
// data, runs the math loop. Zeroes hist for replay idempotence.
// ============================================================================
#define SPLAT_THREADS 128

__global__ __launch_bounds__(SPLAT_THREADS)
void splat_kernel(float* __restrict__ out, int B, int N) {
    __shared__ unsigned s_mask[16];        // 512 bits of candidacy
    __shared__ int s_list[MAX_N];
    __shared__ int s_cnt;
    __shared__ float4 s_ga[GC];
    __shared__ float4 s_gb[GC];
    __shared__ float4 s_sh[GC][8];         // 7 used + 1 pad

    int t = blockIdx.x;
    int tid = threadIdx.x;
    int warp = tid >> 5;
    int lane = tid & 31;

    if (tid == 0) g_hist[t] = 0;           // replay idempotence

    int base = g_base[t];
    int rayEnd = (t == NUM_TILES - 1) ? B : g_base[t + 1];
    int rayCount = rayEnd - base;
    if (rayCount == 0) return;             // block-uniform

    // ---- phase A: parallel bbox tests (4 gaussians per thread, MLP=4) ----
    {
        int tx = t & (TILES_X - 1);
        int ty = t >> 5;
        float x0 = tx * TILE_PX, x1 = x0 + TILE_PX;
        float y0 = ty * TILE_PX, y1 = y0 + TILE_PX;
#pragma unroll
        for (int k = 0; k < 4; ++k) {
            int c = warp * 4 + k;          // chunk 0..15
            int g = c * 32 + lane;
            bool ok = false;
            if (g < N) {
                float4 bb = g_bbox[g];
                ok = (bb.x <= x1) && (bb.y >= x0) && (bb.z <= y1) && (bb.w >= y0);
            }
            unsigned m = __ballot_sync(0xFFFFFFFFu, ok);
            if (lane == 0) s_mask[c] = m;
        }
    }
    __syncthreads();

    // ---- phase B: warp 0 ordered compaction (index-ascending, deterministic)
    if (warp == 0) {
        int cnt = 0;
#pragma unroll
        for (int c = 0; c < 16; ++c) {
            unsigned m = s_mask[c];
            bool ok = (m >> lane) & 1u;
            if (ok) {
                int off = __popc(m & ((1u << lane) - 1u));
                s_list[cnt + off] = c * 32 + lane;
            }
            cnt += __popc(m);
        }
        if (lane == 0) s_cnt = cnt;
    }
    __syncthreads();
    int cnt = s_cnt;

    for (int r0 = 0; r0 < rayCount; r0 += SPLAT_THREADS) {
        int myIdx = r0 + tid;
        bool active = myIdx < rayCount;
        int ray = 0;
        float px = 0.0f, py = 0.0f;
        if (active) {
            float2 xy = g_xy[base + myIdx];    // coalesced
            ray = g_rayid[base + myIdx];
            px = xy.x - (WPIX * 0.5f);
            py = xy.y - (HPIX * 0.5f);
        }
        float sumR = 0.0f, sumG = 0.0f, sumB = 0.0f;

        for (int c0 = 0; c0 < cnt; c0 += GC) {
            int m = min(GC, cnt - c0);
            __syncthreads();
            for (int i = tid; i < m; i += SPLAT_THREADS) {
                int n = s_list[c0 + i];
                s_ga[i] = g_ga[n];
                s_gb[i] = g_gb[n];
            }
            for (int i = tid; i < m * 8; i += SPLAT_THREADS) {
                int sl = i >> 3, j = i & 7;
                if (j < 7) {
                    int n = s_list[c0 + sl];
                    s_sh[sl][j] = g_sh[n * 7 + j];
                }
            }
            __syncthreads();

            if (active) {
                for (int i = 0; i < m; ++i) {
                    float4 ga = s_ga[i];
                    float vx = px - ga.x;
                    float vy = py - ga.y;
                    float svx = vx * ga.z;
                    float svy = vy * ga.w;
                    float d2 = fmaf(svx, svx, svy * svy);
                    if (d2 < 25.0f) {
                        float4 gb = s_gb[i];
                        float c = gb.x, sa = gb.y;
                        float w = __expf(-d2) * gb.z;

                        float rvx = c * vx - sa * vy;
                        float rvy = fmaf(sa, vx, c * vy);
                        float rn = rsqrtf(fmaf(rvx, rvx, fmaf(rvy, rvy, 1e-20f)));
                        float s1 = rvx * rn;   // sin(theta)
                        float c1 = rvy * rn;   // cos(theta)
                        float s2 = 2.0f * s1 * c1;
                        float c2 = fmaf(c1, c1, -s1 * s1);
                        float s3 = fmaf(s1, c2, c1 * s2);
                        float c3 = fmaf(c1, c2, -s1 * s2);
                        float s4 = 2.0f * s2 * c2;
                        float c4 = fmaf(c2, c2, -s2 * s2);

                        float4 q0 = s_sh[i][0], q1 = s_sh[i][1], q2 = s_sh[i][2];
                        float4 q3 = s_sh[i][3], q4 = s_sh[i][4], q5 = s_sh[i][5];
                        float4 q6 = s_sh[i][6];

                        float aR = q0.x;
                        aR = fmaf(s1, q0.w, aR); aR = fmaf(c1, q1.z, aR);
                        aR = fmaf(s2, q2.y, aR); aR = fmaf(c2, q3.x, aR);
                        aR = fmaf(s3, q3.w, aR); aR = fmaf(c3, q4.z, aR);
                        aR = fmaf(s4, q5.y, aR); aR = fmaf(c4, q6.x, aR);
                        float aG = q0.y;
                        aG = fmaf(s1, q1.x, aG); aG = fmaf(c1, q1.w, aG);
                        aG = fmaf(s2, q2.z, aG); aG = fmaf(c2, q3.y, aG);
                        aG = fmaf(s3, q4.x, aG); aG = fmaf(c3, q4.w, aG);
                        aG = fmaf(s4, q5.z, aG); aG = fmaf(c4, q6.y, aG);
                        float aB = q0.z;
                        aB = fmaf(s1, q1.y, aB); aB = fmaf(c1, q2.x, aB);
                        aB = fmaf(s2, q2.w, aB); aB = fmaf(c2, q3.z, aB);
                        aB = fmaf(s3, q4.y, aB); aB = fmaf(c3, q5.x, aB);
                        aB = fmaf(s4, q5.w, aB); aB = fmaf(c4, q6.z, aB);

                        float rR = __fdividef(1.0f, 1.0f + __expf(-aR));
                        float rG = __fdividef(1.0f, 1.0f + __expf(-aG));
                        float rB = __fdividef(1.0f, 1.0f + __expf(-aB));
                        sumR = fmaf(w, rR, sumR);
                        sumG = fmaf(w, rG, sumG);
                        sumB = fmaf(w, rB, sumB);
                    }
                }
            }
        }

        if (active) {
            out[3 * ray + 0] = sumR;
            out[3 * ray + 1] = sumG;
            out[3 * ray + 2] = sumB;
        }
    }
}

extern "C" void kernel_launch(void* const* d_in, const int* in_sizes, int n_in,
                              void* d_out, int out_size) {
    // metadata order: x, rgbsh, opacity, mu, scale, angle
    const float* x       = (const float*)d_in[0];
    const float* rgbsh   = (const float*)d_in[1];
    const float* opacity = (const float*)d_in[2];
    const float* mu      = (const float*)d_in[3];
    const float* scale   = (const float*)d_in[4];
    const float* angle   = (const float*)d_in[5];
    float* out = (float*)d_out;

    int B = in_sizes[0] / 2;
    int N = in_sizes[2];
    if (N > MAX_N) N = MAX_N;

    int binBlocks = (B + 511) / 512;
    prep_kernel<<<binBlocks + 1, 512>>>(x, rgbsh, opacity, mu, scale, angle, B, N, binBlocks);

    scan_scatter_kernel<<<(B + NUM_TILES - 1) / NUM_TILES, NUM_TILES>>>(x, B);

    splat_kernel<<<NUM_TILES, SPLAT_THREADS>>>(out, B, N);
}

// round 8
// speedup vs baseline: 1.1085x; 1.1085x over previous
#include <cuda_runtime.h>
#include <cuda_bf16.h>

// Problem constants (match reference)
#define WPIX 512.0f
#define HPIX 512.0f
#define S_MIN (1.0f / 30.0f)
#define S_MAX (1.0f / 0.75f)
#define MU_BORDER 1.05f
#define PI_APPROX 3.1416f

#define MAX_N 512
#define MAX_B 65536
#define TILE_PX 16.0f
#define TILES_X 32
#define TILES_Y 32
#define NUM_TILES (TILES_X * TILES_Y)
#define GC 64                 // gaussians staged per smem chunk
#define PRE_BLOCKS 16
#define G_PER_BLOCK 32        // 512 / 16

// ---- per-gaussian precomputed data ----
__device__ float4 g_ga[MAX_N];          // (gmx, gmy, Sx, Sy), centered px coords
__device__ float4 g_gb[MAX_N];          // (cos a, sin a, sigmoid(op), 0)
__device__ float4 g_sh[MAX_N * 7];      // repacked 27 SH coeffs + pad
__device__ float4 g_bbox[MAX_N];        // (xmin, xmax, ymin, ymax), raw px

// ---- ray binning (counting sort by tile) ----
__device__ int    g_hist[NUM_TILES];    // .bss zero; re-zeroed by splat each call
__device__ int    g_base[NUM_TILES];
__device__ int    g_rank[MAX_B];
__device__ float2 g_xy[MAX_B];          // sorted ray coords
__device__ int    g_rayid[MAX_B];       // sorted ray ids

__device__ __forceinline__ int tile_of(float xr, float yr) {
    int tx = min(TILES_X - 1, max(0, (int)(xr * (1.0f / TILE_PX))));
    int ty = min(TILES_Y - 1, max(0, (int)(yr * (1.0f / TILE_PX))));
    return ty * TILES_X + tx;
}

// ============================================================================
// K1: blocks [0, binBlocks): ray binning (hist + rank)
//     blocks [binBlocks, binBlocks+PRE_BLOCKS): per-gaussian precompute,
//       32 gaussians per block, fully parallel (no straggler).
// ============================================================================
__global__ __launch_bounds__(512)
void prep_kernel(const float* __restrict__ x,
                 const float* __restrict__ rgbsh,
                 const float* __restrict__ opacity,
                 const float* __restrict__ mu,
                 const float* __restrict__ scale,
                 const float* __restrict__ angle,
                 int B, int N, int binBlocks) {
    int bid = blockIdx.x;
    int tid = threadIdx.x;

    if (bid < binBlocks) {
        int r = bid * 512 + tid;
        if (r < B) {
            float2 xy = ((const float2*)x)[r];
            int t = tile_of(xy.x, xy.y);
            g_rank[r] = atomicAdd(&g_hist[t], 1);
        }
    } else {
        int g0 = (bid - binBlocks) * G_PER_BLOCK;
        if (tid < G_PER_BLOCK) {
            int n = g0 + tid;
            if (n < N) {
                float gmx = tanhf(mu[2 * n + 0]) * (MU_BORDER * WPIX * 0.5f);
                float gmy = tanhf(mu[2 * n + 1]) * (MU_BORDER * HPIX * 0.5f);
                float sx = fminf(fmaxf(scale[2 * n + 0], 0.0f), 1.0f) * (S_MAX - S_MIN) + S_MIN;
                float sy = fminf(fmaxf(scale[2 * n + 1], 0.0f), 1.0f) * (S_MAX - S_MIN) + S_MIN;
                g_ga[n] = make_float4(gmx, gmy, sx, sy);

                float hx = __fdividef(5.0f, sx) + 0.05f;   // fp-rounding margin
                float hy = __fdividef(5.0f, sy) + 0.05f;
                float cx = gmx + WPIX * 0.5f;
                float cy = gmy + HPIX * 0.5f;
                g_bbox[n] = make_float4(cx - hx, cx + hx, cy - hy, cy + hy);

                float alpha = tanhf(angle[n]) * PI_APPROX;
                float c, s;
                sincosf(alpha, &s, &c);
                float op = 1.0f / (1.0f + expf(-opacity[n]));
                g_gb[n] = make_float4(c, s, op, 0.0f);
            }
        } else if (tid < G_PER_BLOCK + G_PER_BLOCK * 7) {
            // SH repack: one float4 slot per thread (224 tasks)
            int task = tid - G_PER_BLOCK;
            int sl = task / 7;          // local gaussian
            int j = task - sl * 7;      // slot 0..6
            int n = g0 + sl;
            if (n < N) {
                int c0 = 4 * j;
                float v0 = rgbsh[n * 27 + c0];
                float v1 = (c0 + 1 < 27) ? rgbsh[n * 27 + c0 + 1] : 0.0f;
                float v2 = (c0 + 2 < 27) ? rgbsh[n * 27 + c0 + 2] : 0.0f;
                float v3 = (c0 + 3 < 27) ? rgbsh[n * 27 + c0 + 3] : 0.0f;
                g_sh[n * 7 + j] = make_float4(v0, v1, v2, v3);
            }
        }
    }
}

// ============================================================================
// K2: every block scans the 1024-bin histogram (warp-shuffle scan, 2 syncs),
// then scatters its 1024-ray slice into sorted order (coords + id).
// Block 0 publishes g_base.
// ============================================================================
__global__ __launch_bounds__(NUM_TILES)
void scan_scatter_kernel(const float* __restrict__ x, int B) {
    __shared__ int s_wsum[32];
    __shared__ int sbase[NUM_TILES];
    int t = threadIdx.x;
    int lane = t & 31;
    int warp = t >> 5;

    int h = g_hist[t];
    // warp-inclusive scan
    int incl = h;
#pragma unroll
    for (int d = 1; d < 32; d <<= 1) {
        int v = __shfl_up_sync(0xFFFFFFFFu, incl, d);
        if (lane >= d) incl += v;
    }
    if (lane == 31) s_wsum[warp] = incl;
    __syncthreads();
    if (warp == 0) {
        int w = s_wsum[lane];
        int wi = w;
#pragma unroll
        for (int d = 1; d < 32; d <<= 1) {
            int v = __shfl_up_sync(0xFFFFFFFFu, wi, d);
            if (lane >= d) wi += v;
        }
        s_wsum[lane] = wi - w;   // exclusive warp offsets
    }
    __syncthreads();
    int myBase = incl - h + s_wsum[warp];   // exclusive scan result
    sbase[t] = myBase;
    if (blockIdx.x == 0) g_base[t] = myBase;
    __syncthreads();

    int r = blockIdx.x * NUM_TILES + t;
    if (r < B) {
        float2 xy = ((const float2*)x)[r];
        int tr = tile_of(xy.x, xy.y);
        int pos = sbase[tr] + g_rank[r];
        g_xy[pos] = xy;
        g_rayid[pos] = r;
    }
}

// ============================================================================
// K3: splat — one block per tile. Builds its own gaussian list inline in smem
// (parallel bbox tests -> ballot masks -> ordered compaction), stages gaussian
// data, runs the math loop. Zeroes hist for replay idempotence.
// ============================================================================
#define SPLAT_THREADS 128

__global__ __launch_bounds__(SPLAT_THREADS)
void splat_kernel(float* __restrict__ out, int B, int N) {
    __shared__ unsigned s_mask[16];        // 512 bits of candidacy
    __shared__ int s_list[MAX_N];
    __shared__ int s_cnt;
    __shared__ float4 s_ga[GC];
    __shared__ float4 s_gb[GC];
    __shared__ float4 s_sh[GC][8];         // 7 used + 1 pad

    int t = blockIdx.x;
    int tid = threadIdx.x;
    int warp = tid >> 5;
    int lane = tid & 31;

    if (tid == 0) g_hist[t] = 0;           // replay idempotence

    int base = g_base[t];
    int rayEnd = (t == NUM_TILES - 1) ? B : g_base[t + 1];
    int rayCount = rayEnd - base;
    if (rayCount == 0) return;             // block-uniform

    // ---- phase A: parallel bbox tests (4 gaussians per thread, MLP=4) ----
    {
        int tx = t & (TILES_X - 1);
        int ty = t >> 5;
        float x0 = tx * TILE_PX, x1 = x0 + TILE_PX;
        float y0 = ty * TILE_PX, y1 = y0 + TILE_PX;
#pragma unroll
        for (int k = 0; k < 4; ++k) {
            int c = warp * 4 + k;          // chunk 0..15
            int g = c * 32 + lane;
            bool ok = false;
            if (g < N) {
                float4 bb = g_bbox[g];
                ok = (bb.x <= x1) && (bb.y >= x0) && (bb.z <= y1) && (bb.w >= y0);
            }
            unsigned m = __ballot_sync(0xFFFFFFFFu, ok);
            if (lane == 0) s_mask[c] = m;
        }
    }
    __syncthreads();

    // ---- phase B: warp 0 ordered compaction (index-ascending, deterministic)
    if (warp == 0) {
        int cnt = 0;
#pragma unroll
        for (int c = 0; c < 16; ++c) {
            unsigned m = s_mask[c];
            bool ok = (m >> lane) & 1u;
            if (ok) {
                int off = __popc(m & ((1u << lane) - 1u));
                s_list[cnt + off] = c * 32 + lane;
            }
            cnt += __popc(m);
        }
        if (lane == 0) s_cnt = cnt;
    }
    __syncthreads();
    int cnt = s_cnt;

    for (int r0 = 0; r0 < rayCount; r0 += SPLAT_THREADS) {
        int myIdx = r0 + tid;
        bool active = myIdx < rayCount;
        int ray = 0;
        float px = 0.0f, py = 0.0f;
        if (active) {
            float2 xy = g_xy[base + myIdx];    // coalesced
            ray = g_rayid[base + myIdx];
            px = xy.x - (WPIX * 0.5f);
            py = xy.y - (HPIX * 0.5f);
        }
        float sumR = 0.0f, sumG = 0.0f, sumB = 0.0f;

        for (int c0 = 0; c0 < cnt; c0 += GC) {
            int m = min(GC, cnt - c0);
            __syncthreads();
            for (int i = tid; i < m; i += SPLAT_THREADS) {
                int n = s_list[c0 + i];
                s_ga[i] = g_ga[n];
                s_gb[i] = g_gb[n];
            }
            for (int i = tid; i < m * 8; i += SPLAT_THREADS) {
                int sl = i >> 3, j = i & 7;
                if (j < 7) {
                    int n = s_list[c0 + sl];
                    s_sh[sl][j] = g_sh[n * 7 + j];
                }
            }
            __syncthreads();

            if (active) {
                for (int i = 0; i < m; ++i) {
                    float4 ga = s_ga[i];
                    float vx = px - ga.x;
                    float vy = py - ga.y;
                    float svx = vx * ga.z;
                    float svy = vy * ga.w;
                    float d2 = fmaf(svx, svx, svy * svy);
                    if (d2 < 25.0f) {
                        float4 gb = s_gb[i];
                        float c = gb.x, sa = gb.y;
                        float w = __expf(-d2) * gb.z;

                        float rvx = c * vx - sa * vy;
                        float rvy = fmaf(sa, vx, c * vy);
                        float rn = rsqrtf(fmaf(rvx, rvx, fmaf(rvy, rvy, 1e-20f)));
                        float s1 = rvx * rn;   // sin(theta)
                        float c1 = rvy * rn;   // cos(theta)
                        float s2 = 2.0f * s1 * c1;
                        float c2 = fmaf(c1, c1, -s1 * s1);
                        float s3 = fmaf(s1, c2, c1 * s2);
                        float c3 = fmaf(c1, c2, -s1 * s2);
                        float s4 = 2.0f * s2 * c2;
                        float c4 = fmaf(c2, c2, -s2 * s2);

                        float4 q0 = s_sh[i][0], q1 = s_sh[i][1], q2 = s_sh[i][2];
                        float4 q3 = s_sh[i][3], q4 = s_sh[i][4], q5 = s_sh[i][5];
                        float4 q6 = s_sh[i][6];

                        float aR = q0.x;
                        aR = fmaf(s1, q0.w, aR); aR = fmaf(c1, q1.z, aR);
                        aR = fmaf(s2, q2.y, aR); aR = fmaf(c2, q3.x, aR);
                        aR = fmaf(s3, q3.w, aR); aR = fmaf(c3, q4.z, aR);
                        aR = fmaf(s4, q5.y, aR); aR = fmaf(c4, q6.x, aR);
                        float aG = q0.y;
                        aG = fmaf(s1, q1.x, aG); aG = fmaf(c1, q1.w, aG);
                        aG = fmaf(s2, q2.z, aG); aG = fmaf(c2, q3.y, aG);
                        aG = fmaf(s3, q4.x, aG); aG = fmaf(c3, q4.w, aG);
                        aG = fmaf(s4, q5.z, aG); aG = fmaf(c4, q6.y, aG);
                        float aB = q0.z;
                        aB = fmaf(s1, q1.y, aB); aB = fmaf(c1, q2.x, aB);
                        aB = fmaf(s2, q2.w, aB); aB = fmaf(c2, q3.z, aB);
                        aB = fmaf(s3, q4.y, aB); aB = fmaf(c3, q5.x, aB);
                        aB = fmaf(s4, q5.w, aB); aB = fmaf(c4, q6.z, aB);

                        float rR = __fdividef(1.0f, 1.0f + __expf(-aR));
                        float rG = __fdividef(1.0f, 1.0f + __expf(-aG));
                        float rB = __fdividef(1.0f, 1.0f + __expf(-aB));
                        sumR = fmaf(w, rR, sumR);
                        sumG = fmaf(w, rG, sumG);
                        sumB = fmaf(w, rB, sumB);
                    }
                }
            }
        }

        if (active) {
            out[3 * ray + 0] = sumR;
            out[3 * ray + 1] = sumG;
            out[3 * ray + 2] = sumB;
        }
    }
}

extern "C" void kernel_launch(void* const* d_in, const int* in_sizes, int n_in,
                              void* d_out, int out_size) {
    // metadata order: x, rgbsh, opacity, mu, scale, angle
    const float* x       = (const float*)d_in[0];
    const float* rgbsh   = (const float*)d_in[1];
    const float* opacity = (const float*)d_in[2];
    const float* mu      = (const float*)d_in[3];
    const float* scale   = (const float*)d_in[4];
    const float* angle   = (const float*)d_in[5];
    float* out = (float*)d_out;

    int B = in_sizes[0] / 2;
    int N = in_sizes[2];
    if (N > MAX_N) N = MAX_N;

    int binBlocks = (B + 511) / 512;
    prep_kernel<<<binBlocks + PRE_BLOCKS, 512>>>(x, rgbsh, opacity, mu, scale, angle, B, N, binBlocks);

    scan_scatter_kernel<<<(B + NUM_TILES - 1) / NUM_TILES, NUM_TILES>>>(x, B);

    splat_kernel<<<NUM_TILES, SPLAT_THREADS>>>(out, B, N);
}

// round 9
// speedup vs baseline: 1.2411x; 1.1196x over previous
#include <cuda_runtime.h>
#include <cuda_bf16.h>

// Problem constants (match reference)
#define WPIX 512.0f
#define HPIX 512.0f
#define S_MIN (1.0f / 30.0f)
#define S_MAX (1.0f / 0.75f)
#define MU_BORDER 1.05f
#define PI_APPROX 3.1416f

#define MAX_N 512
#define MAX_B 65536
#define TILE_PX 16.0f
#define TILES_X 32
#define TILES_Y 32
#define NUM_TILES (TILES_X * TILES_Y)
#define GC 64                 // gaussians staged per smem chunk
#define PRE_BLOCKS 16
#define G_PER_BLOCK 32        // 512 / 16
#define CAP 256               // bucket capacity per tile (mean load = 32)

// ---- per-gaussian precomputed data ----
__device__ float4 g_ga[MAX_N];          // (gmx, gmy, Sx, Sy), centered px coords
__device__ float4 g_gb[MAX_N];          // (cos a, sin a, sigmoid(op), 0)
__device__ float4 g_sh[MAX_N * 7];      // repacked 27 SH coeffs + pad
__device__ float4 g_bbox[MAX_N];        // (xmin, xmax, ymin, ymax), raw px

// ---- direct ray buckets ----
__device__ int    g_hist[NUM_TILES];    // .bss zero; re-zeroed by splat each call
__device__ float2 g_bxy[NUM_TILES * CAP];
__device__ int    g_bid[NUM_TILES * CAP];
// overflow (correctness fallback; empty for benchmark inputs)
__device__ int    g_ovf_cnt;
__device__ float2 g_ovf_xy[MAX_B];
__device__ int    g_ovf_id[MAX_B];

__device__ __forceinline__ int tile_of(float xr, float yr) {
    int tx = min(TILES_X - 1, max(0, (int)(xr * (1.0f / TILE_PX))));
    int ty = min(TILES_Y - 1, max(0, (int)(yr * (1.0f / TILE_PX))));
    return ty * TILES_X + tx;
}

// shared per-pair math (identical FP sequence everywhere)
__device__ __forceinline__ void splat_accum(
    float px, float py, float4 ga, float4 gb,
    const float4 q0, const float4 q1, const float4 q2, const float4 q3,
    const float4 q4, const float4 q5, const float4 q6,
    float& sumR, float& sumG, float& sumB)
{
    float vx = px - ga.x;
    float vy = py - ga.y;
    float svx = vx * ga.z;
    float svy = vy * ga.w;
    float d2 = fmaf(svx, svx, svy * svy);
    if (d2 < 25.0f) {
        float c = gb.x, sa = gb.y;
        float w = __expf(-d2) * gb.z;

        float rvx = c * vx - sa * vy;
        float rvy = fmaf(sa, vx, c * vy);
        float rn = rsqrtf(fmaf(rvx, rvx, fmaf(rvy, rvy, 1e-20f)));
        float s1 = rvx * rn;   // sin(theta)
        float c1 = rvy * rn;   // cos(theta)
        float s2 = 2.0f * s1 * c1;
        float c2 = fmaf(c1, c1, -s1 * s1);
        float s3 = fmaf(s1, c2, c1 * s2);
        float c3 = fmaf(c1, c2, -s1 * s2);
        float s4 = 2.0f * s2 * c2;
        float c4 = fmaf(c2, c2, -s2 * s2);

        float aR = q0.x;
        aR = fmaf(s1, q0.w, aR); aR = fmaf(c1, q1.z, aR);
        aR = fmaf(s2, q2.y, aR); aR = fmaf(c2, q3.x, aR);
        aR = fmaf(s3, q3.w, aR); aR = fmaf(c3, q4.z, aR);
        aR = fmaf(s4, q5.y, aR); aR = fmaf(c4, q6.x, aR);
        float aG = q0.y;
        aG = fmaf(s1, q1.x, aG); aG = fmaf(c1, q1.w, aG);
        aG = fmaf(s2, q2.z, aG); aG = fmaf(c2, q3.y, aG);
        aG = fmaf(s3, q4.x, aG); aG = fmaf(c3, q4.w, aG);
        aG = fmaf(s4, q5.z, aG); aG = fmaf(c4, q6.y, aG);
        float aB = q0.z;
        aB = fmaf(s1, q1.y, aB); aB = fmaf(c1, q2.x, aB);
        aB = fmaf(s2, q2.w, aB); aB = fmaf(c2, q3.z, aB);
        aB = fmaf(s3, q4.y, aB); aB = fmaf(c3, q5.x, aB);
        aB = fmaf(s4, q5.w, aB); aB = fmaf(c4, q6.z, aB);

        float rR = __fdividef(1.0f, 1.0f + __expf(-aR));
        float rG = __fdividef(1.0f, 1.0f + __expf(-aG));
        float rB = __fdividef(1.0f, 1.0f + __expf(-aB));
        sumR = fmaf(w, rR, sumR);
        sumG = fmaf(w, rG, sumG);
        sumB = fmaf(w, rB, sumB);
    }
}

// ============================================================================
// K1: blocks [0, binBlocks): ray binning -> direct bucket scatter (4 rays/thr)
//     blocks [binBlocks, binBlocks+PRE_BLOCKS): per-gaussian precompute
// ============================================================================
__global__ __launch_bounds__(512)
void prep_kernel(const float* __restrict__ x,
                 const float* __restrict__ rgbsh,
                 const float* __restrict__ opacity,
                 const float* __restrict__ mu,
                 const float* __restrict__ scale,
                 const float* __restrict__ angle,
                 int B, int N, int binBlocks) {
    int bid = blockIdx.x;
    int tid = threadIdx.x;

    if (bid < binBlocks) {
        const float4* x4 = (const float4*)x;
        int gthr = bid * 512 + tid;         // thread handles float4s 2g, 2g+1
#pragma unroll
        for (int k = 0; k < 2; ++k) {
            int f = 2 * gthr + k;           // float4 index = rays 2f, 2f+1
            if (2 * f < B) {
                float4 v = x4[f];
#pragma unroll
                for (int j = 0; j < 2; ++j) {
                    int r = 2 * f + j;
                    if (r < B) {
                        float xr = (j == 0) ? v.x : v.z;
                        float yr = (j == 0) ? v.y : v.w;
                        int t = tile_of(xr, yr);
                        int pos = atomicAdd(&g_hist[t], 1);
                        if (pos < CAP) {
                            g_bxy[t * CAP + pos] = make_float2(xr, yr);
                            g_bid[t * CAP + pos] = r;
                        } else {
                            int o = atomicAdd(&g_ovf_cnt, 1);
                            g_ovf_xy[o] = make_float2(xr, yr);
                            g_ovf_id[o] = r;
                        }
                    }
                }
            }
        }
    } else {
        int g0 = (bid - binBlocks) * G_PER_BLOCK;
        if (tid < G_PER_BLOCK) {
            int n = g0 + tid;
            if (n < N) {
                float gmx = tanhf(mu[2 * n + 0]) * (MU_BORDER * WPIX * 0.5f);
                float gmy = tanhf(mu[2 * n + 1]) * (MU_BORDER * HPIX * 0.5f);
                float sx = fminf(fmaxf(scale[2 * n + 0], 0.0f), 1.0f) * (S_MAX - S_MIN) + S_MIN;
                float sy = fminf(fmaxf(scale[2 * n + 1], 0.0f), 1.0f) * (S_MAX - S_MIN) + S_MIN;
                g_ga[n] = make_float4(gmx, gmy, sx, sy);

                float hx = __fdividef(5.0f, sx) + 0.05f;   // fp-rounding margin
                float hy = __fdividef(5.0f, sy) + 0.05f;
                float cx = gmx + WPIX * 0.5f;
                float cy = gmy + HPIX * 0.5f;
                g_bbox[n] = make_float4(cx - hx, cx + hx, cy - hy, cy + hy);

                float alpha = tanhf(angle[n]) * PI_APPROX;
                float c, s;
                sincosf(alpha, &s, &c);
                float op = 1.0f / (1.0f + expf(-opacity[n]));
                g_gb[n] = make_float4(c, s, op, 0.0f);
            }
        } else if (tid < G_PER_BLOCK + G_PER_BLOCK * 7) {
            int task = tid - G_PER_BLOCK;
            int sl = task / 7;
            int j = task - sl * 7;
            int n = g0 + sl;
            if (n < N) {
                int c0 = 4 * j;
                float v0 = rgbsh[n * 27 + c0];
                float v1 = (c0 + 1 < 27) ? rgbsh[n * 27 + c0 + 1] : 0.0f;
                float v2 = (c0 + 2 < 27) ? rgbsh[n * 27 + c0 + 2] : 0.0f;
                float v3 = (c0 + 3 < 27) ? rgbsh[n * 27 + c0 + 3] : 0.0f;
                g_sh[n * 7 + j] = make_float4(v0, v1, v2, v3);
            }
        }
    }
}

// ============================================================================
// K2: splat — block t < NUM_TILES: inline list build + bucket rays.
//     block NUM_TILES: overflow fallback (empty in practice).
// ============================================================================
#define SPLAT_THREADS 128

__global__ __launch_bounds__(SPLAT_THREADS)
void splat_kernel(float* __restrict__ out, int B, int N) {
    int t = blockIdx.x;
    int tid = threadIdx.x;

    if (t == NUM_TILES) {
        // overflow fallback: brute force over all gaussians
        int nOvf = g_ovf_cnt;
        __syncthreads();
        if (tid == 0) g_ovf_cnt = 0;
        for (int i = tid; i < nOvf; i += SPLAT_THREADS) {
            int cap = (nOvf < MAX_B) ? nOvf : MAX_B;
            if (i >= cap) break;
            float2 xy = g_ovf_xy[i];
            int ray = g_ovf_id[i];
            float px = xy.x - (WPIX * 0.5f);
            float py = xy.y - (HPIX * 0.5f);
            float sumR = 0.0f, sumG = 0.0f, sumB = 0.0f;
            for (int n = 0; n < N; ++n) {
                float4 ga = g_ga[n];
                float4 gb = g_gb[n];
                const float4* sh = &g_sh[n * 7];
                splat_accum(px, py, ga, gb, sh[0], sh[1], sh[2], sh[3],
                            sh[4], sh[5], sh[6], sumR, sumG, sumB);
            }
            out[3 * ray + 0] = sumR;
            out[3 * ray + 1] = sumG;
            out[3 * ray + 2] = sumB;
        }
        return;
    }

    __shared__ unsigned s_mask[16];        // 512 bits of candidacy
    __shared__ int s_list[MAX_N];
    __shared__ int s_cnt;
    __shared__ float4 s_ga[GC];
    __shared__ float4 s_gb[GC];
    __shared__ float4 s_sh[GC][8];         // 7 used + 1 pad

    int warp = tid >> 5;
    int lane = tid & 31;

    int hist = g_hist[t];
    int rayCount = (hist < CAP) ? hist : CAP;

    // ---- phase A: parallel bbox tests (4 gaussians per thread, MLP=4) ----
    if (rayCount > 0) {
        int tx = t & (TILES_X - 1);
        int ty = t >> 5;
        float x0 = tx * TILE_PX, x1 = x0 + TILE_PX;
        float y0 = ty * TILE_PX, y1 = y0 + TILE_PX;
#pragma unroll
        for (int k = 0; k < 4; ++k) {
            int c = warp * 4 + k;          // chunk 0..15
            int g = c * 32 + lane;
            bool ok = false;
            if (g < N) {
                float4 bb = g_bbox[g];
                ok = (bb.x <= x1) && (bb.y >= x0) && (bb.z <= y1) && (bb.w >= y0);
            }
            unsigned m = __ballot_sync(0xFFFFFFFFu, ok);
            if (lane == 0) s_mask[c] = m;
        }
    }
    __syncthreads();
    if (tid == 0) g_hist[t] = 0;           // replay idempotence (after reads)
    if (rayCount == 0) return;

    // ---- phase B: warp 0 ordered compaction (index-ascending, deterministic)
    if (warp == 0) {
        int cnt = 0;
#pragma unroll
        for (int c = 0; c < 16; ++c) {
            unsigned m = s_mask[c];
            bool ok = (m >> lane) & 1u;
            if (ok) {
                int off = __popc(m & ((1u << lane) - 1u));
                s_list[cnt + off] = c * 32 + lane;
            }
            cnt += __popc(m);
        }
        if (lane == 0) s_cnt = cnt;
    }
    __syncthreads();
    int cnt = s_cnt;
    int bbase = t * CAP;

    for (int r0 = 0; r0 < rayCount; r0 += SPLAT_THREADS) {
        int myIdx = r0 + tid;
        bool active = myIdx < rayCount;
        int ray = 0;
        float px = 0.0f, py = 0.0f;
        if (active) {
            float2 xy = g_bxy[bbase + myIdx];    // coalesced
            ray = g_bid[bbase + myIdx];
            px = xy.x - (WPIX * 0.5f);
            py = xy.y - (HPIX * 0.5f);
        }
        float sumR = 0.0f, sumG = 0.0f, sumB = 0.0f;

        for (int c0 = 0; c0 < cnt; c0 += GC) {
            int m = min(GC, cnt - c0);
            __syncthreads();
            for (int i = tid; i < m; i += SPLAT_THREADS) {
                int n = s_list[c0 + i];
                s_ga[i] = g_ga[n];
                s_gb[i] = g_gb[n];
            }
            for (int i = tid; i < m * 8; i += SPLAT_THREADS) {
                int sl = i >> 3, j = i & 7;
                if (j < 7) {
                    int n = s_list[c0 + sl];
                    s_sh[sl][j] = g_sh[n * 7 + j];
                }
            }
            __syncthreads();

            if (active) {
                for (int i = 0; i < m; ++i) {
                    splat_accum(px, py, s_ga[i], s_gb[i],
                                s_sh[i][0], s_sh[i][1], s_sh[i][2], s_sh[i][3],
                                s_sh[i][4], s_sh[i][5], s_sh[i][6],
                                sumR, sumG, sumB);
                }
            }
        }

        if (active) {
            out[3 * ray + 0] = sumR;
            out[3 * ray + 1] = sumG;
            out[3 * ray + 2] = sumB;
        }
    }
}

extern "C" void kernel_launch(void* const* d_in, const int* in_sizes, int n_in,
                              void* d_out, int out_size) {
    // metadata order: x, rgbsh, opacity, mu, scale, angle
    const float* x       = (const float*)d_in[0];
    const float* rgbsh   = (const float*)d_in[1];
    const float* opacity = (const float*)d_in[2];
    const float* mu      = (const float*)d_in[3];
    const float* scale   = (const float*)d_in[4];
    const float* angle   = (const float*)d_in[5];
    float* out = (float*)d_out;

    int B = in_sizes[0] / 2;
    int N = in_sizes[2];
    if (N > MAX_N) N = MAX_N;

    // 4 rays per thread, 2048 rays per block
    int binBlocks = (B + 2047) / 2048;
    prep_kernel<<<binBlocks + PRE_BLOCKS, 512>>>(x, rgbsh, opacity, mu, scale, angle, B, N, binBlocks);

    splat_kernel<<<NUM_TILES + 1, SPLAT_THREADS>>>(out, B, N);
}